// round 17
// baseline (speedup 1.0000x reference)
#include <cuda_runtime.h>
#include <cuda_bf16.h>
#include <math.h>
#include <float.h>
#include <stdint.h>

#define NROWS   8192
#define IN_DIM  256
#define DIM     128
#define KCODES  8192
#define MBOOK   8
#define EPSBN   1e-5f

// output layout: x_hat [8192,256] ++ res_s [8,8192,128] ++ ce_s [8,8192,128]
#define RES_OFF ((size_t)NROWS * IN_DIM)
#define CE_OFF  (RES_OFF + (size_t)MBOOK * NROWS * DIM)

// scratch (static device allocations only)
__device__ float g_h1[NROWS * 128];
__device__ float g_h2[NROWS * 256];
__device__ float g_ze[NROWS * DIM];
__device__ float g_di[NROWS * DIM];
__device__ float g_t1[NROWS * 256];
__device__ float g_t2[NROWS * 128];
__device__ float g_nn[MBOOK * KCODES];                 // ||e||^2 fp32
__device__ __nv_bfloat16 g_cbh[MBOOK * KCODES * DIM];  // bf16 hi limb of E

// ---------------------------------------------------------------------------
// mma.sync / ldmatrix helpers (baseline PTX, compiles for compute_103)
// ---------------------------------------------------------------------------
#define MMA16816(d0,d1,d2,d3,a0,a1,a2,a3,b0,b1) \
    asm volatile("mma.sync.aligned.m16n8k16.row.col.f32.bf16.bf16.f32 " \
        "{%0,%1,%2,%3}, {%4,%5,%6,%7}, {%8,%9}, {%0,%1,%2,%3};" \
        : "+f"(d0), "+f"(d1), "+f"(d2), "+f"(d3) \
        : "r"(a0), "r"(a1), "r"(a2), "r"(a3), "r"(b0), "r"(b1))

#define LDSM4(r0,r1,r2,r3,addr) \
    asm volatile("ldmatrix.sync.aligned.m8n8.x4.shared.b16 {%0,%1,%2,%3}, [%4];" \
        : "=r"(r0), "=r"(r1), "=r"(r2), "=r"(r3) : "r"(addr))

__device__ __forceinline__ uint32_t smem_u32(const void* p) {
    uint32_t a;
    asm("{ .reg .u64 t; cvta.to.shared.u64 t, %1; cvt.u32.u64 %0, t; }"
        : "=r"(a) : "l"(p));
    return a;
}

__device__ __forceinline__ uint32_t pack_bf16f(float a, float b) {
    return (uint32_t)__bfloat16_as_ushort(__float2bfloat16(a))
         | ((uint32_t)__bfloat16_as_ushort(__float2bfloat16(b)) << 16);
}

// top-2 running-min insert
__device__ __forceinline__ void top2(float s, int c,
    float& b1, float& b2, int& i1, int& i2)
{
    if (s < b2) {
        if (s < b1) { b2 = b1; i2 = i1; b1 = s; i1 = c; }
        else        { b2 = s;  i2 = c; }
    }
}

// ---------------------------------------------------------------------------
// Tiled GEMM: C = act(bn(A[N,KD] @ W[KD,P] + bias))
// 32x64 block tile (micro 2x4), 256 threads — grid 512/1024 CTAs so the
// short fixed kernels aren't wave-limited. Per-element K order identical
// to the 64x64 version (sequential k) -> bit-identical outputs.
// ---------------------------------------------------------------------------
template<int KD, int P, bool BN, bool RELU>
__global__ void __launch_bounds__(256, 4) gemm_kernel(
    const float* __restrict__ A, const float* __restrict__ W,
    const float* __restrict__ bias,
    const float* __restrict__ gg, const float* __restrict__ be,
    const float* __restrict__ rm, const float* __restrict__ rv,
    float* __restrict__ C)
{
    __shared__ __align__(16) float As[16][36];   // [kk][row], 32 rows
    __shared__ __align__(16) float Ws[16][68];   // [kk][col], 64 cols
    const int tid = threadIdx.x;
    const int rid = tid >> 4, cid = tid & 15;
    const int row0 = blockIdx.y * 32, col0 = blockIdx.x * 64;
    float acc[2][4] = {};

    for (int k0 = 0; k0 < KD; k0 += 16) {
        __syncthreads();
        #pragma unroll
        for (int i = 0; i < 2; i++) {            // As: 512 floats
            int idx = tid + i * 256;
            int r = idx >> 4, kk = idx & 15;
            As[kk][r] = A[(size_t)(row0 + r) * KD + (k0 + kk)];
        }
        #pragma unroll
        for (int i = 0; i < 4; i++) {            // Ws: 1024 floats
            int idx = tid + i * 256;
            int kk2 = idx >> 6, c = idx & 63;
            Ws[kk2][c] = W[(size_t)(k0 + kk2) * P + (col0 + c)];
        }
        __syncthreads();
        #pragma unroll
        for (int kk = 0; kk < 16; kk++) {
            float2 a = *(const float2*)&As[kk][rid * 2];
            float4 w = *(const float4*)&Ws[kk][cid * 4];
            float av[2] = {a.x, a.y};
            float wv[4] = {w.x, w.y, w.z, w.w};
            #pragma unroll
            for (int r = 0; r < 2; r++)
                #pragma unroll
                for (int c = 0; c < 4; c++)
                    acc[r][c] += av[r] * wv[c];
        }
    }
    #pragma unroll
    for (int r = 0; r < 2; r++) {
        int row = row0 + rid * 2 + r;
        #pragma unroll
        for (int c = 0; c < 4; c++) {
            int col = col0 + cid * 4 + c;
            float v = acc[r][c] + bias[col];
            if constexpr (BN)
                v = (v - rm[col]) / sqrtf(rv[col] + EPSBN) * gg[col] + be[col];
            if constexpr (RELU)
                v = fmaxf(v, 0.0f);
            C[(size_t)row * P + col] = v;
        }
    }
}

// ---------------------------------------------------------------------------
// fused codebook prep: ||e||^2 (per-thread sequential order) + bf16 hi-limb
// ---------------------------------------------------------------------------
__global__ void prep_kernel(const float* __restrict__ cbk)
{
    int i = blockIdx.x * 256 + threadIdx.x;            // code id < MBOOK*KCODES
    const float4* p = (const float4*)(cbk + (size_t)i * DIM);
    uint2* dst = (uint2*)(g_cbh + (size_t)i * DIM);
    float s = 0.f;
    #pragma unroll
    for (int j = 0; j < DIM / 4; j++) {
        float4 q = p[j];
        s += q.x * q.x + q.y * q.y + q.z * q.z + q.w * q.w;
        uint2 u;
        u.x = pack_bf16f(q.x, q.y);
        u.y = pack_bf16f(q.z, q.w);
        dst[j] = u;
    }
    g_nn[i] = s;
}

// ---------------------------------------------------------------------------
// Residual VQ v17 = v16 with 4 independent MMA accumulator chains
//  (hh-only bf16 mma.sync, 32 rows/CTA, grid 256, 2 CTAs/SM, 2-buffer
//   cp.async + smem ee, top-2/thread + exact fp32 rescore).
// ---------------------------------------------------------------------------
#define VROWS 32
#define TC    128
#define NT    (KCODES / TC)
#define RES_STRIDE 132
#define EBUF_B (TC * 256)                  // 32768 bytes per buffer

// smem byte offsets
#define SM_RES  0                          // 32*132*4 = 16896
#define SM_RRS  16896                      // 32 floats (pad to 128)
#define SM_CAND 17024                      // 32*32 ints = 4096
#define SM_BIDX 21120                      // 32 ints (pad to 128)
#define SM_EE   21248                      // 2 x 128 floats = 1024
#define SM_EBUF 22272                      // 2 * EBUF_B
#define SM_TOTAL (SM_EBUF + 2 * EBUF_B)    // 87808

__device__ __forceinline__ void stageE(uint32_t ebuf_sm, uint32_t ee_sm,
                                       const __nv_bfloat16* __restrict__ bh,
                                       const float* __restrict__ nb,
                                       int tile, int tid)
{
    #pragma unroll
    for (int i = 0; i < 8; i++) {
        int ch = tid + i * 256;                   // 0..2047
        int code = ch >> 4, g = ch & 15;
        const __nv_bfloat16* src = bh + ((size_t)(tile * TC + code) << 7) + (g << 3);
        uint32_t dst = ebuf_sm + code * 256 + ((g ^ (code & 7)) << 4);
        asm volatile("cp.async.cg.shared.global [%0], [%1], 16;"
                     :: "r"(dst), "l"(src));
    }
    if (tid < 32) {
        const float* esrc = nb + tile * TC + tid * 4;
        asm volatile("cp.async.cg.shared.global [%0], [%1], 16;"
                     :: "r"(ee_sm + tid * 16), "l"(esrc));
    }
    asm volatile("cp.async.commit_group;");
}

__global__ void __launch_bounds__(256, 2) vq_kernel(
    const float* __restrict__ ze, const float* __restrict__ cbk,
    float* __restrict__ out)
{
    extern __shared__ char smc[];
    float* res     = (float*)(smc + SM_RES);
    float* rr_s    = (float*)(smc + SM_RRS);
    int*   cand    = (int*)(smc + SM_CAND);
    int*   bestIdx = (int*)(smc + SM_BIDX);
    float* ee_sm   = (float*)(smc + SM_EE);
    const uint32_t sb_ee   = smem_u32(smc + SM_EE);
    const uint32_t sb_ebuf = smem_u32(smc + SM_EBUF);

    const int tid  = threadIdx.x;
    const int warp = tid >> 5, lane = tid & 31;
    const int row0 = blockIdx.x * VROWS;
    const int rg   = warp >> 2;                 // rowgroup (16 rows)
    const int chf  = warp & 3;                  // code quarter within tile (32)
    const int tig  = lane & 3, gid = lane >> 2;
    const int r_lo = rg * 16 + gid, r_hi = r_lo + 8;
    const int codeL = chf * 32 + (lane & 7);    // smem code row this lane reads
    const int grnb  = lane >> 3;                // 0..3 (x4 block id)
    const int cs    = lane & 7;                 // swizzle key (codeL & 7)

    // residual := ze  (32 rows x 128 dims = 1024 float4)
    #pragma unroll
    for (int i = 0; i < 4; i++) {
        int g = tid + i * 256;
        int r = g >> 5, dq = g & 31;
        *(float4*)(res + r * RES_STRIDE + dq * 4) =
            *(const float4*)(ze + (size_t)(row0 + r) * DIM + dq * 4);
    }
    __syncthreads();

    for (int m = 0; m < MBOOK; m++) {
        const float* Eb = cbk + (size_t)m * KCODES * DIM;
        const float* nb = g_nn + m * KCODES;
        const __nv_bfloat16* bh = g_cbh + (size_t)m * KCODES * DIM;

        // prime the pipeline: tile 0
        stageE(sb_ebuf, sb_ee, bh, nb, 0, tid);

        // emit res_s[m]
        {
            size_t ob = RES_OFF + (size_t)m * NROWS * DIM + (size_t)row0 * DIM;
            #pragma unroll
            for (int i = 0; i < 4; i++) {
                int g = tid + i * 256;
                int r = g >> 5, dq = g & 31;
                *(float4*)(out + ob + (size_t)r * DIM + dq * 4) =
                    *(const float4*)(res + r * RES_STRIDE + dq * 4);
            }
        }

        // per-row ||r||^2 (sequential dim order)
        if (tid < VROWS) {
            float s = 0.f;
            #pragma unroll
            for (int dq = 0; dq < 32; dq++) {
                float4 v = *(const float4*)(res + tid * RES_STRIDE + dq * 4);
                s = fmaf(v.x, v.x, s); s = fmaf(v.y, v.y, s);
                s = fmaf(v.z, v.z, s); s = fmaf(v.w, v.w, s);
            }
            rr_s[tid] = s;
        }
        __syncthreads();

        const float rr_lo = rr_s[r_lo], rr_hi = rr_s[r_hi];

        // build A hi-limb fragments in registers from res smem
        uint32_t Ah[8][4];
        #pragma unroll
        for (int ks = 0; ks < 8; ks++) {
            int c0 = ks * 16 + 2 * tig;
            const float* pl = res + r_lo * RES_STRIDE + c0;
            const float* ph = res + r_hi * RES_STRIDE + c0;
            Ah[ks][0] = pack_bf16f(pl[0], pl[1]);
            Ah[ks][1] = pack_bf16f(ph[0], ph[1]);
            Ah[ks][2] = pack_bf16f(pl[8], pl[9]);
            Ah[ks][3] = pack_bf16f(ph[8], ph[9]);
        }

        // top-2 approx candidates per thread for each of its 2 rows
        float b1l = FLT_MAX, b2l = FLT_MAX, b1h = FLT_MAX, b2h = FLT_MAX;
        int   i1l = 0x7fffffff, i2l = 0x7fffffff;
        int   i1h = 0x7fffffff, i2h = 0x7fffffff;

        for (int t = 0; t < NT; t++) {
            // wait for tile t's staging, make visible, then prefetch t+1
            asm volatile("cp.async.wait_group 0;");
            __syncthreads();                    // single barrier per tile
            if (t + 1 < NT)
                stageE(sb_ebuf + ((t + 1) & 1) * EBUF_B,
                       sb_ee + ((t + 1) & 1) * 512, bh, nb, t + 1, tid);

            const uint32_t ebuf = sb_ebuf + (t & 1) * EBUF_B;
            const float* ee = ee_sm + (t & 1) * 128;
            const int tbase = t * TC + chf * 32;

            #pragma unroll
            for (int ng = 0; ng < 4; ng++) {
                const uint32_t rowa = ebuf + (codeL + ng * 8) * 256;
                // four independent accumulator chains (one per kp)
                float c0a = 0.f, c0b = 0.f, c0c = 0.f, c0d = 0.f;
                float c1a = 0.f, c1b = 0.f, c1c = 0.f, c1d = 0.f;
                float c2a = 0.f, c2b = 0.f, c2c = 0.f, c2d = 0.f;
                float c3a = 0.f, c3b = 0.f, c3c = 0.f, c3d = 0.f;

                {
                    uint32_t goff, h0, h1, h2, h3;
                    goff = (uint32_t)(((0 * 4 + grnb) ^ cs) << 4);
                    LDSM4(h0, h1, h2, h3, rowa + goff);
                    MMA16816(c0a,c0b,c0c,c0d, Ah[0][0],Ah[0][1],Ah[0][2],Ah[0][3], h0,h1);
                    MMA16816(c0a,c0b,c0c,c0d, Ah[1][0],Ah[1][1],Ah[1][2],Ah[1][3], h2,h3);
                    goff = (uint32_t)(((1 * 4 + grnb) ^ cs) << 4);
                    LDSM4(h0, h1, h2, h3, rowa + goff);
                    MMA16816(c1a,c1b,c1c,c1d, Ah[2][0],Ah[2][1],Ah[2][2],Ah[2][3], h0,h1);
                    MMA16816(c1a,c1b,c1c,c1d, Ah[3][0],Ah[3][1],Ah[3][2],Ah[3][3], h2,h3);
                    goff = (uint32_t)(((2 * 4 + grnb) ^ cs) << 4);
                    LDSM4(h0, h1, h2, h3, rowa + goff);
                    MMA16816(c2a,c2b,c2c,c2d, Ah[4][0],Ah[4][1],Ah[4][2],Ah[4][3], h0,h1);
                    MMA16816(c2a,c2b,c2c,c2d, Ah[5][0],Ah[5][1],Ah[5][2],Ah[5][3], h2,h3);
                    goff = (uint32_t)(((3 * 4 + grnb) ^ cs) << 4);
                    LDSM4(h0, h1, h2, h3, rowa + goff);
                    MMA16816(c3a,c3b,c3c,c3d, Ah[6][0],Ah[6][1],Ah[6][2],Ah[6][3], h0,h1);
                    MMA16816(c3a,c3b,c3c,c3d, Ah[7][0],Ah[7][1],Ah[7][2],Ah[7][3], h2,h3);
                }

                // fold chains; approx scores (ee from smem, bitwise == g_nn)
                float d0 = (c0a + c1a) + (c2a + c3a);
                float d1 = (c0b + c1b) + (c2b + c3b);
                float d2 = (c0c + c1c) + (c2c + c3c);
                float d3 = (c0d + c1d) + (c2d + c3d);
                const int cA = tbase + ng * 8 + 2 * tig;
                const float eeA = ee[chf * 32 + ng * 8 + 2 * tig];
                const float eeB = ee[chf * 32 + ng * 8 + 2 * tig + 1];
                top2(fmaf(-2.0f, d0, rr_lo) + eeA, cA,     b1l,b2l, i1l,i2l);
                top2(fmaf(-2.0f, d1, rr_lo) + eeB, cA + 1, b1l,b2l, i1l,i2l);
                top2(fmaf(-2.0f, d2, rr_hi) + eeA, cA,     b1h,b2h, i1h,i2h);
                top2(fmaf(-2.0f, d3, rr_hi) + eeB, cA + 1, b1h,b2h, i1h,i2h);
            }
        }
        __syncthreads();

        // deposit candidates: 16 threads/row x 2 = 32 slots/row
        {
            int slot = (chf * 4 + tig) * 2;
            cand[r_lo * 32 + slot]     = i1l;
            cand[r_lo * 32 + slot + 1] = i2l;
            cand[r_hi * 32 + slot]     = i1h;
            cand[r_hi * 32 + slot + 1] = i2h;
        }
        __syncthreads();

        // exact fp32 rescore of the 32 candidates per row (reference rounding)
        #pragma unroll 1
        for (int rw = 0; rw < VROWS / 8; rw++) {
            int row = warp * 4 + rw;
            int c = cand[row * 32 + lane];
            const float4* e  = (const float4*)(Eb + (size_t)c * DIM);
            const float4* rp = (const float4*)(res + row * RES_STRIDE);
            float p = 0.f;
            #pragma unroll
            for (int i = 0; i < 32; i++) {
                float4 rv = rp[i];
                float4 ev = __ldg(e + i);
                p = fmaf(rv.x, ev.x, p); p = fmaf(rv.y, ev.y, p);
                p = fmaf(rv.z, ev.z, p); p = fmaf(rv.w, ev.w, p);
            }
            float dd = fmaf(-2.0f, p, rr_s[row]) + __ldg(g_nn + (size_t)m * KCODES + c);
            float bv = dd; int bi = c;
            #pragma unroll
            for (int off = 16; off >= 1; off >>= 1) {
                float ov = __shfl_down_sync(0xffffffffu, bv, off);
                int   oi = __shfl_down_sync(0xffffffffu, bi, off);
                if (ov < bv || (ov == bv && oi < bi)) { bv = ov; bi = oi; }
            }
            if (lane == 0) bestIdx[row] = bi;
        }
        __syncthreads();

        // quantize: emit ce_s[m], residual -= ce (fp32 codebook, exact)
        #pragma unroll 1
        for (int rw = 0; rw < VROWS / 8; rw++) {
            int row = warp * 4 + rw;
            int idx = bestIdx[row];
            float4 cv = __ldg((const float4*)(Eb + (size_t)idx * DIM) + lane);
            size_t ob = CE_OFF + (size_t)m * NROWS * DIM
                      + (size_t)(row0 + row) * DIM;
            *(float4*)(out + ob + lane * 4) = cv;
            float4* rp = (float4*)(res + row * RES_STRIDE + lane * 4);
            float4 rv = *rp;
            rv.x -= cv.x; rv.y -= cv.y; rv.z -= cv.z; rv.w -= cv.w;
            *rp = rv;
        }
        __syncthreads();
    }
}

// ---------------------------------------------------------------------------
// di = ze + (sum_m ce_s[m] - ze)
// ---------------------------------------------------------------------------
__global__ void di_kernel(const float* __restrict__ out)
{
    int i = blockIdx.x * 256 + threadIdx.x;
    float zev = g_ze[i];
    float zq = 0.f;
    #pragma unroll
    for (int m = 0; m < MBOOK; m++)
        zq += out[CE_OFF + (size_t)m * NROWS * DIM + i];
    g_di[i] = zev + (zq - zev);
}

// ---------------------------------------------------------------------------
extern "C" void kernel_launch(void* const* d_in, const int* in_sizes, int n_in,
                              void* d_out, int out_size)
{
    const float* x   = (const float*)d_in[0];
    const float* W1  = (const float*)d_in[1];
    const float* b1  = (const float*)d_in[2];
    const float* g1  = (const float*)d_in[3];
    const float* be1 = (const float*)d_in[4];
    const float* rm1 = (const float*)d_in[5];
    const float* rv1 = (const float*)d_in[6];
    const float* W2  = (const float*)d_in[7];
    const float* b2  = (const float*)d_in[8];
    const float* g2  = (const float*)d_in[9];
    const float* be2 = (const float*)d_in[10];
    const float* rm2 = (const float*)d_in[11];
    const float* rv2 = (const float*)d_in[12];
    const float* W3  = (const float*)d_in[13];
    const float* b3  = (const float*)d_in[14];
    const float* cbk = (const float*)d_in[15];
    const float* W4  = (const float*)d_in[16];
    const float* b4  = (const float*)d_in[17];
    const float* g3  = (const float*)d_in[18];
    const float* be3 = (const float*)d_in[19];
    const float* rm3 = (const float*)d_in[20];
    const float* rv3 = (const float*)d_in[21];
    const float* W5  = (const float*)d_in[22];
    const float* b5  = (const float*)d_in[23];
    const float* g4  = (const float*)d_in[24];
    const float* be4 = (const float*)d_in[25];
    const float* rm4 = (const float*)d_in[26];
    const float* rv4 = (const float*)d_in[27];
    const float* W6  = (const float*)d_in[28];
    const float* b6  = (const float*)d_in[29];
    float* out = (float*)d_out;

    float *h1, *h2, *ze, *di, *t1, *t2;
    cudaGetSymbolAddress((void**)&h1, g_h1);
    cudaGetSymbolAddress((void**)&h2, g_h2);
    cudaGetSymbolAddress((void**)&ze, g_ze);
    cudaGetSymbolAddress((void**)&di, g_di);
    cudaGetSymbolAddress((void**)&t1, g_t1);
    cudaGetSymbolAddress((void**)&t2, g_t2);

    cudaFuncSetAttribute(vq_kernel,
                         cudaFuncAttributeMaxDynamicSharedMemorySize, SM_TOTAL);

    // fused codebook prep (single pass)
    prep_kernel<<<MBOOK * KCODES / 256, 256>>>(cbk);

    // encoder (32x64 tiles -> grids 512/1024 CTAs)
    gemm_kernel<256, 128, true,  true ><<<dim3(2, 256), 256>>>(x,  W1, b1, g1, be1, rm1, rv1, h1);
    gemm_kernel<128, 256, true,  true ><<<dim3(4, 256), 256>>>(h1, W2, b2, g2, be2, rm2, rv2, h2);
    gemm_kernel<256, 128, false, false><<<dim3(2, 256), 256>>>(h2, W3, b3, nullptr, nullptr, nullptr, nullptr, ze);

    // residual VQ
    vq_kernel<<<NROWS / VROWS, 256, SM_TOTAL>>>(ze, cbk, out);

    // straight-through: di = ze + (zq - ze)
    di_kernel<<<NROWS * DIM / 256, 256>>>(out);

    // decoder
    gemm_kernel<128, 256, true,  true ><<<dim3(4, 256), 256>>>(di, W4, b4, g3, be3, rm3, rv3, t1);
    gemm_kernel<256, 128, true,  true ><<<dim3(2, 256), 256>>>(t1, W5, b5, g4, be4, rm4, rv4, t2);
    gemm_kernel<128, 256, false, false><<<dim3(4, 256), 256>>>(t2, W6, b6, nullptr, nullptr, nullptr, nullptr, out);
}